// round 3
// baseline (speedup 1.0000x reference)
#include <cuda_runtime.h>
#include <cstdint>

#define HIDDEN   1024
#define NUM_HEADS 16
#define HEAD_SZ   64
#define BATCH      2
#define SEQ     2048
#define MTOT    (BATCH * SEQ)          // 4096
#define QKV_N   (3 * HIDDEN)           // 3072

// Scratch (allocation-free rule: __device__ globals)
__device__ float g_qkv[(size_t)MTOT * QKV_N];   // 48 MB
__device__ float g_av [(size_t)MTOT * HIDDEN];  // 16 MB

// ---------------------------------------------------------------------------
// tf32 helpers
// ---------------------------------------------------------------------------
__device__ __forceinline__ uint32_t f2tf(float x) {
    uint32_t r;
    asm("cvt.rna.tf32.f32 %0, %1;" : "=r"(r) : "f"(x));
    return r;
}
__device__ __forceinline__ float f2tf_f(float x) { return __uint_as_float(f2tf(x)); }

__device__ __forceinline__ void mma_tf32(float c[4],
    uint32_t a0, uint32_t a1, uint32_t a2, uint32_t a3,
    uint32_t b0, uint32_t b1)
{
    asm volatile(
        "mma.sync.aligned.m16n8k8.row.col.f32.tf32.tf32.f32 "
        "{%0,%1,%2,%3}, {%4,%5,%6,%7}, {%8,%9}, {%0,%1,%2,%3};\n"
        : "+f"(c[0]), "+f"(c[1]), "+f"(c[2]), "+f"(c[3])
        : "r"(a0), "r"(a1), "r"(a2), "r"(a3), "r"(b0), "r"(b1));
}

// ---------------------------------------------------------------------------
// TF32 GEMM: C[M,N] = A[M,K] @ B[K,N] + bias
// Block 128x128, BK=32, 256 threads = 8 warps (2 x 4), warp tile 64x32.
// ---------------------------------------------------------------------------
__global__ __launch_bounds__(256) void gemm_tf32(
    const float* __restrict__ A, const float* __restrict__ B,
    const float* __restrict__ bias, float* __restrict__ C,
    int M, int N, int K)
{
    __shared__ float As[128][36];   // pitch 36: conflict-free frag reads
    __shared__ float Bs[32][136];   // pitch 136: conflict-free frag reads

    const int tid  = threadIdx.x;
    const int warp = tid >> 5, lane = tid & 31;
    const int wm = warp >> 2, wn = warp & 3;      // 2 x 4 warp grid
    const int g = lane >> 2, tig = lane & 3;
    const int row0 = blockIdx.y * 128, col0 = blockIdx.x * 128;

    const float* Ag = A + (size_t)row0 * K;
    const float* Bg = B + col0;

    const int a_r = tid >> 3, a_c = (tid & 7) * 4;   // + p*32 rows
    const int b_r = tid >> 5, b_c = (tid & 31) * 4;  // + p*8 rows

    float acc[4][4][4];
#pragma unroll
    for (int mt = 0; mt < 4; mt++)
#pragma unroll
        for (int nt = 0; nt < 4; nt++)
#pragma unroll
            for (int i = 0; i < 4; i++) acc[mt][nt][i] = 0.0f;

    float4 aS[4], bS[4];

    // prologue load k0 = 0
#pragma unroll
    for (int p = 0; p < 4; p++) {
        aS[p] = *(const float4*)(Ag + (size_t)(p * 32 + a_r) * K + a_c);
        bS[p] = *(const float4*)(Bg + (size_t)(p * 8 + b_r) * N + b_c);
    }
#pragma unroll
    for (int p = 0; p < 4; p++) {
        float4 a = aS[p], b = bS[p];
        float4 ac4 = make_float4(f2tf_f(a.x), f2tf_f(a.y), f2tf_f(a.z), f2tf_f(a.w));
        float4 bc4 = make_float4(f2tf_f(b.x), f2tf_f(b.y), f2tf_f(b.z), f2tf_f(b.w));
        *(float4*)&As[p * 32 + a_r][a_c] = ac4;
        *(float4*)&Bs[p * 8 + b_r][b_c] = bc4;
    }
    __syncthreads();

    for (int k0 = 0; k0 < K; k0 += 32) {
        const bool more = (k0 + 32) < K;
        if (more) {
#pragma unroll
            for (int p = 0; p < 4; p++) {
                aS[p] = *(const float4*)(Ag + (size_t)(p * 32 + a_r) * K + k0 + 32 + a_c);
                bS[p] = *(const float4*)(Bg + (size_t)(k0 + 32 + p * 8 + b_r) * N + b_c);
            }
        }

#pragma unroll
        for (int kk = 0; kk < 4; kk++) {
            uint32_t af[4][4], bf[4][2];
            const int cA = kk * 8 + tig;
#pragma unroll
            for (int mt = 0; mt < 4; mt++) {
                const int r = wm * 64 + mt * 16 + g;
                af[mt][0] = __float_as_uint(As[r][cA]);
                af[mt][1] = __float_as_uint(As[r + 8][cA]);
                af[mt][2] = __float_as_uint(As[r][cA + 4]);
                af[mt][3] = __float_as_uint(As[r + 8][cA + 4]);
            }
#pragma unroll
            for (int nt = 0; nt < 4; nt++) {
                const int cB = wn * 32 + nt * 8 + g;
                bf[nt][0] = __float_as_uint(Bs[kk * 8 + tig][cB]);
                bf[nt][1] = __float_as_uint(Bs[kk * 8 + tig + 4][cB]);
            }
#pragma unroll
            for (int mt = 0; mt < 4; mt++)
#pragma unroll
                for (int nt = 0; nt < 4; nt++)
                    mma_tf32(acc[mt][nt], af[mt][0], af[mt][1], af[mt][2], af[mt][3],
                             bf[nt][0], bf[nt][1]);
        }
        __syncthreads();
        if (more) {
#pragma unroll
            for (int p = 0; p < 4; p++) {
                float4 a = aS[p], b = bS[p];
                float4 ac4 = make_float4(f2tf_f(a.x), f2tf_f(a.y), f2tf_f(a.z), f2tf_f(a.w));
                float4 bc4 = make_float4(f2tf_f(b.x), f2tf_f(b.y), f2tf_f(b.z), f2tf_f(b.w));
                *(float4*)&As[p * 32 + a_r][a_c] = ac4;
                *(float4*)&Bs[p * 8 + b_r][b_c] = bc4;
            }
            __syncthreads();
        }
    }

    // Epilogue with bias (c0,c1 at row g; c2,c3 at row g+8; cols tig*2, tig*2+1)
#pragma unroll
    for (int mt = 0; mt < 4; mt++) {
        const int r_lo = row0 + wm * 64 + mt * 16 + g;
        const int r_hi = r_lo + 8;
#pragma unroll
        for (int nt = 0; nt < 4; nt++) {
            const int col = col0 + wn * 32 + nt * 8 + tig * 2;
            const float b0 = bias[col], b1 = bias[col + 1];
            float2 lo = make_float2(acc[mt][nt][0] + b0, acc[mt][nt][1] + b1);
            float2 hi = make_float2(acc[mt][nt][2] + b0, acc[mt][nt][3] + b1);
            *(float2*)(C + (size_t)r_lo * N + col) = lo;
            *(float2*)(C + (size_t)r_hi * N + col) = hi;
        }
    }
}

// ---------------------------------------------------------------------------
// TF32 flash attention.
// Grid: (SEQ/128, BATCH*NUM_HEADS), 256 threads = 8 warps.
// Warp w owns query rows [w*16, w*16+16) of the 128-query tile -> softmax
// rows never cross warps. Q fragments persist in registers; K/V 64-key
// tiles staged in smem (tf32). Scores->P layout fix via register shuffles.
// ---------------------------------------------------------------------------
__global__ __launch_bounds__(256) void attn_tf32()
{
    // Pool: Ks[64][68] + Vs[64][72]  (8960 floats). Qs[128][68] aliases pool
    // during the prologue only (8704 <= 8960).
    __shared__ float pool[64 * 68 + 64 * 72];
    float (*Ks)[68] = (float(*)[68])pool;
    float (*Vs)[72] = (float(*)[72])(pool + 64 * 68);
    float (*Qs)[68] = (float(*)[68])pool;

    const int tid = threadIdx.x;
    const int warp = tid >> 5, lane = tid & 31;
    const int g = lane >> 2, tig = lane & 3;
    const int bh = blockIdx.y;
    const int b = bh >> 4, h = bh & 15;
    const int q0 = blockIdx.x * 128;

    const float* base = g_qkv + (size_t)b * SEQ * QKV_N;

    // ---- Prologue: load Q tile (scaled by 1/sqrt(64), tf32) ----
    {
        const int r = tid >> 4, c4 = (tid & 15) * 4;
#pragma unroll
        for (int p = 0; p < 8; p++) {
            const int row = p * 16 + r;
            float4 v = *(const float4*)(base + (size_t)(q0 + row) * QKV_N + h * HEAD_SZ + c4);
            float4 s = make_float4(f2tf_f(v.x * 0.125f), f2tf_f(v.y * 0.125f),
                                   f2tf_f(v.z * 0.125f), f2tf_f(v.w * 0.125f));
            *(float4*)&Qs[row][c4] = s;
        }
    }
    __syncthreads();

    // Build Q fragments: 8 k-steps (d = 0..63), rows warp*16 + g (+8)
    uint32_t qf[8][4];
    {
        const int rb = warp * 16;
#pragma unroll
        for (int ks = 0; ks < 8; ks++) {
            const int c = ks * 8 + tig;
            qf[ks][0] = __float_as_uint(Qs[rb + g][c]);
            qf[ks][1] = __float_as_uint(Qs[rb + 8 + g][c]);
            qf[ks][2] = __float_as_uint(Qs[rb + g][c + 4]);
            qf[ks][3] = __float_as_uint(Qs[rb + 8 + g][c + 4]);
        }
    }
    __syncthreads();   // pool will be overwritten by K/V

    float o[8][4];
#pragma unroll
    for (int nt = 0; nt < 8; nt++)
#pragma unroll
        for (int i = 0; i < 4; i++) o[nt][i] = 0.0f;
    float m_lo = -1e30f, m_hi = -1e30f;
    float l_lo = 0.0f, l_hi = 0.0f;

    const int lr = tid >> 4, lc4 = (tid & 15) * 4;

    for (int kb = 0; kb < SEQ; kb += 64) {
        // ---- Load K and V tiles (64 x 64 each), tf32 ----
#pragma unroll
        for (int p = 0; p < 4; p++) {
            const int row = p * 16 + lr;
            const float* kr = base + (size_t)(kb + row) * QKV_N + HIDDEN + h * HEAD_SZ + lc4;
            const float* vr = base + (size_t)(kb + row) * QKV_N + 2 * HIDDEN + h * HEAD_SZ + lc4;
            float4 kv = *(const float4*)kr;
            float4 vv = *(const float4*)vr;
            *(float4*)&Ks[row][lc4] = make_float4(f2tf_f(kv.x), f2tf_f(kv.y), f2tf_f(kv.z), f2tf_f(kv.w));
            *(float4*)&Vs[row][lc4] = make_float4(f2tf_f(vv.x), f2tf_f(vv.y), f2tf_f(vv.z), f2tf_f(vv.w));
        }
        __syncthreads();

        // ---- S = Q @ K^T : per warp 16 x 64, 8 key-tiles of 8 ----
        float c[8][4];
#pragma unroll
        for (int nt = 0; nt < 8; nt++) {
            c[nt][0] = c[nt][1] = c[nt][2] = c[nt][3] = 0.0f;
#pragma unroll
            for (int ks = 0; ks < 8; ks++) {
                uint32_t b0 = __float_as_uint(Ks[nt * 8 + g][ks * 8 + tig]);
                uint32_t b1 = __float_as_uint(Ks[nt * 8 + g][ks * 8 + tig + 4]);
                mma_tf32(c[nt], qf[ks][0], qf[ks][1], qf[ks][2], qf[ks][3], b0, b1);
            }
        }

        // ---- Online softmax: row max (rows = g and g+8, shared by 4-lane group) ----
        float tmx_lo = -1e30f, tmx_hi = -1e30f;
#pragma unroll
        for (int nt = 0; nt < 8; nt++) {
            tmx_lo = fmaxf(tmx_lo, fmaxf(c[nt][0], c[nt][1]));
            tmx_hi = fmaxf(tmx_hi, fmaxf(c[nt][2], c[nt][3]));
        }
        tmx_lo = fmaxf(tmx_lo, __shfl_xor_sync(0xffffffffu, tmx_lo, 1));
        tmx_lo = fmaxf(tmx_lo, __shfl_xor_sync(0xffffffffu, tmx_lo, 2));
        tmx_hi = fmaxf(tmx_hi, __shfl_xor_sync(0xffffffffu, tmx_hi, 1));
        tmx_hi = fmaxf(tmx_hi, __shfl_xor_sync(0xffffffffu, tmx_hi, 2));

        const float mn_lo = fmaxf(m_lo, tmx_lo);
        const float mn_hi = fmaxf(m_hi, tmx_hi);
        const float al_lo = __expf(m_lo - mn_lo);
        const float al_hi = __expf(m_hi - mn_hi);
        m_lo = mn_lo; m_hi = mn_hi;
        l_lo *= al_lo; l_hi *= al_hi;
#pragma unroll
        for (int nt = 0; nt < 8; nt++) {
            o[nt][0] *= al_lo; o[nt][1] *= al_lo;
            o[nt][2] *= al_hi; o[nt][3] *= al_hi;
        }

        // ---- P @ V : for each 8-key chunk, shuffle scores into A-frag layout ----
        const int srcA = (lane & ~3) | (tig >> 1);
        const int srcB = srcA | 2;
        const bool oddc = (tig & 1);
#pragma unroll
        for (int ks = 0; ks < 8; ks++) {
            float v00 = __shfl_sync(0xffffffffu, c[ks][0], srcA);
            float v01 = __shfl_sync(0xffffffffu, c[ks][1], srcA);
            float w00 = __shfl_sync(0xffffffffu, c[ks][0], srcB);
            float w01 = __shfl_sync(0xffffffffu, c[ks][1], srcB);
            float v10 = __shfl_sync(0xffffffffu, c[ks][2], srcA);
            float v11 = __shfl_sync(0xffffffffu, c[ks][3], srcA);
            float w10 = __shfl_sync(0xffffffffu, c[ks][2], srcB);
            float w11 = __shfl_sync(0xffffffffu, c[ks][3], srcB);

            float s0 = oddc ? v01 : v00;   // row g,   key tig
            float s2 = oddc ? w01 : w00;   // row g,   key tig+4
            float s1 = oddc ? v11 : v10;   // row g+8, key tig
            float s3 = oddc ? w11 : w10;   // row g+8, key tig+4

            float p0 = __expf(s0 - m_lo);
            float p2 = __expf(s2 - m_lo);
            float p1 = __expf(s1 - m_hi);
            float p3 = __expf(s3 - m_hi);
            l_lo += p0 + p2;
            l_hi += p1 + p3;

            uint32_t a0 = f2tf(p0), a1 = f2tf(p1), a2 = f2tf(p2), a3 = f2tf(p3);
#pragma unroll
            for (int nd = 0; nd < 8; nd++) {
                uint32_t b0 = __float_as_uint(Vs[ks * 8 + tig][nd * 8 + g]);
                uint32_t b1 = __float_as_uint(Vs[ks * 8 + tig + 4][nd * 8 + g]);
                mma_tf32(o[nd], a0, a1, a2, a3, b0, b1);
            }
        }
        __syncthreads();   // before next tile overwrites Ks/Vs
    }

    // ---- Final normalization + store ----
    l_lo += __shfl_xor_sync(0xffffffffu, l_lo, 1);
    l_lo += __shfl_xor_sync(0xffffffffu, l_lo, 2);
    l_hi += __shfl_xor_sync(0xffffffffu, l_hi, 1);
    l_hi += __shfl_xor_sync(0xffffffffu, l_hi, 2);
    const float inv_lo = 1.0f / l_lo;
    const float inv_hi = 1.0f / l_hi;

    const int r_lo = q0 + warp * 16 + g;
    const int r_hi = r_lo + 8;
    float* avb = g_av + (size_t)b * SEQ * HIDDEN + h * HEAD_SZ;
#pragma unroll
    for (int nd = 0; nd < 8; nd++) {
        const int col = nd * 8 + tig * 2;
        *(float2*)(avb + (size_t)r_lo * HIDDEN + col) =
            make_float2(o[nd][0] * inv_lo, o[nd][1] * inv_lo);
        *(float2*)(avb + (size_t)r_hi * HIDDEN + col) =
            make_float2(o[nd][2] * inv_hi, o[nd][3] * inv_hi);
    }
}

// ---------------------------------------------------------------------------
// Launch
// ---------------------------------------------------------------------------
extern "C" void kernel_launch(void* const* d_in, const int* in_sizes, int n_in,
                              void* d_out, int out_size)
{
    const float* x     = (const float*)d_in[0];
    const float* W_qkv = (const float*)d_in[1];
    const float* b_qkv = (const float*)d_in[2];
    const float* W_o   = (const float*)d_in[3];
    const float* b_o   = (const float*)d_in[4];
    float* out = (float*)d_out;

    float* qkv;
    float* av;
    cudaGetSymbolAddress((void**)&qkv, g_qkv);
    cudaGetSymbolAddress((void**)&av, g_av);

    // 1) qkv = x @ W_qkv + b_qkv   [4096 x 3072]
    {
        dim3 grid(QKV_N / 128, MTOT / 128);
        gemm_tf32<<<grid, 256>>>(x, W_qkv, b_qkv, qkv, MTOT, QKV_N, HIDDEN);
    }
    // 2) attention -> av  [4096 x 1024]
    {
        dim3 grid(SEQ / 128, BATCH * NUM_HEADS);
        attn_tf32<<<grid, 256>>>();
    }
    // 3) out = av @ W_o + b_o  [4096 x 1024]
    {
        dim3 grid(HIDDEN / 128, MTOT / 128);
        gemm_tf32<<<grid, 256>>>(av, W_o, b_o, out, MTOT, HIDDEN, HIDDEN);
    }
}

// round 5
// speedup vs baseline: 1.5282x; 1.5282x over previous
#include <cuda_runtime.h>
#include <cuda_fp16.h>
#include <cstdint>

#define HIDDEN   1024
#define NUM_HEADS 16
#define HEAD_SZ   64
#define BATCH      2
#define SEQ     2048
#define MTOT    (BATCH * SEQ)
#define QKV_N   (3 * HIDDEN)

// Scratch (allocation-free rule: __device__ globals), fp16
__device__ __half g_qkv[(size_t)MTOT * QKV_N];                                // 24 MB
__device__ __half g_av [(size_t)MTOT * HIDDEN];                               // 8 MB
__device__ __half g_wt [(size_t)QKV_N * HIDDEN + (size_t)HIDDEN * HIDDEN];    // 10 MB

// ---------------- helpers ----------------
__device__ __forceinline__ uint32_t smem_u32(const void* p) {
    uint32_t a;
    asm("{ .reg .u64 t; cvta.to.shared.u64 t, %1; cvt.u32.u64 %0, t; }" : "=r"(a) : "l"(p));
    return a;
}
__device__ __forceinline__ uint32_t pack2(float lo, float hi) {
    __half2 h = __floats2half2_rn(lo, hi);
    return *(uint32_t*)&h;
}
__device__ __forceinline__ void mma_f16(float c[4],
    uint32_t a0, uint32_t a1, uint32_t a2, uint32_t a3, uint32_t b0, uint32_t b1)
{
    asm volatile(
        "mma.sync.aligned.m16n8k16.row.col.f32.f16.f16.f32 "
        "{%0,%1,%2,%3}, {%4,%5,%6,%7}, {%8,%9}, {%0,%1,%2,%3};\n"
        : "+f"(c[0]), "+f"(c[1]), "+f"(c[2]), "+f"(c[3])
        : "r"(a0), "r"(a1), "r"(a2), "r"(a3), "r"(b0), "r"(b1));
}
#define LDSM4(r0, r1, r2, r3, addr) \
    asm volatile("ldmatrix.sync.aligned.m8n8.x4.shared.b16 {%0,%1,%2,%3}, [%4];" \
        : "=r"(r0), "=r"(r1), "=r"(r2), "=r"(r3) : "r"(addr))
#define LDSM4T(r0, r1, r2, r3, addr) \
    asm volatile("ldmatrix.sync.aligned.m8n8.x4.trans.shared.b16 {%0,%1,%2,%3}, [%4];" \
        : "=r"(r0), "=r"(r1), "=r"(r2), "=r"(r3) : "r"(addr))

// ---------------- transpose W[R][C] (fp32) -> T[C][R] (fp16) ----------------
__global__ __launch_bounds__(256) void transpose_h(
    const float* __restrict__ W, __half* __restrict__ T, int R, int C)
{
    __shared__ float t[32][33];
    const int tx = threadIdx.x & 31, ty = threadIdx.x >> 5;
    const int c0 = blockIdx.x * 32, r0 = blockIdx.y * 32;
#pragma unroll
    for (int j = 0; j < 4; j++)
        t[ty + 8 * j][tx] = W[(size_t)(r0 + ty + 8 * j) * C + c0 + tx];
    __syncthreads();
#pragma unroll
    for (int j = 0; j < 4; j++)
        T[(size_t)(c0 + ty + 8 * j) * R + r0 + tx] = __float2half(t[tx][ty + 8 * j]);
}

// ---------------- fp16 GEMM: C[M,N] = A[M,K] @ BT[N,K]^T + bias ----------------
// Block 128x128, BK=32, 8 warps (2x4), warp tile 64x32, ldmatrix fragments.
// Smem pitch 40 halves (80B): 16B-aligned rows, conflict-free ldmatrix.
template<bool AH, bool CH>
__global__ __launch_bounds__(256) void gemm_h(
    const void* __restrict__ Ap, const __half* __restrict__ BT,
    const float* __restrict__ bias, void* __restrict__ Cp,
    int M, int N, int K)
{
    __shared__ __half As[128][40];
    __shared__ __half Bs[128][40];

    const int tid = threadIdx.x, warp = tid >> 5, lane = tid & 31;
    const int wm = warp >> 2, wn = warp & 3;
    const int g = lane >> 2, tig = lane & 3;
    const int row0 = blockIdx.y * 128, col0 = blockIdx.x * 128;
    const int frow = tid >> 3, kq = (tid & 7) * 4;

    const __half* Ah = (const __half*)Ap + (size_t)(row0 + frow) * K + kq;
    const float*  Af = (const float*)Ap + (size_t)(row0 + frow) * K + kq;
    const __half* Bh = BT + (size_t)(col0 + frow) * K + kq;

    float acc[4][4][4];
#pragma unroll
    for (int mt = 0; mt < 4; mt++)
#pragma unroll
        for (int nt = 0; nt < 4; nt++)
#pragma unroll
            for (int i = 0; i < 4; i++) acc[mt][nt][i] = 0.0f;

    const uint32_t aBase = smem_u32(&As[0][0]) +
        (uint32_t)((wm * 64 + (lane & 7) + ((lane >> 3) & 1) * 8) * 80 + (lane >> 4) * 16);
    const uint32_t bBase = smem_u32(&Bs[0][0]) +
        (uint32_t)((wn * 32 + (lane & 7) + (lane >> 4) * 8) * 80 + ((lane >> 3) & 1) * 16);

    uint2 aS[4], bS[4];
#pragma unroll
    for (int it = 0; it < 4; it++) {
        if (AH) aS[it] = *(const uint2*)(Ah + (size_t)(it * 32) * K);
        else {
            float4 v = *(const float4*)(Af + (size_t)(it * 32) * K);
            aS[it] = make_uint2(pack2(v.x, v.y), pack2(v.z, v.w));
        }
        bS[it] = *(const uint2*)(Bh + (size_t)(it * 32) * K);
    }

    const int nk = K >> 5;
    for (int kc = 0; kc < nk; kc++) {
#pragma unroll
        for (int it = 0; it < 4; it++) {
            *(uint2*)&As[it * 32 + frow][kq] = aS[it];
            *(uint2*)&Bs[it * 32 + frow][kq] = bS[it];
        }
        __syncthreads();
        if (kc + 1 < nk) {
            const int ko = (kc + 1) * 32;
#pragma unroll
            for (int it = 0; it < 4; it++) {
                if (AH) aS[it] = *(const uint2*)(Ah + (size_t)(it * 32) * K + ko);
                else {
                    float4 v = *(const float4*)(Af + (size_t)(it * 32) * K + ko);
                    aS[it] = make_uint2(pack2(v.x, v.y), pack2(v.z, v.w));
                }
                bS[it] = *(const uint2*)(Bh + (size_t)(it * 32) * K + ko);
            }
        }
#pragma unroll
        for (int kk = 0; kk < 2; kk++) {
            uint32_t af[4][4], bf[4][2];
#pragma unroll
            for (int mt = 0; mt < 4; mt++)
                LDSM4(af[mt][0], af[mt][1], af[mt][2], af[mt][3],
                      aBase + mt * 1280 + kk * 32);
#pragma unroll
            for (int ntp = 0; ntp < 2; ntp++)
                LDSM4(bf[2 * ntp][0], bf[2 * ntp][1], bf[2 * ntp + 1][0], bf[2 * ntp + 1][1],
                      bBase + ntp * 1280 + kk * 32);
#pragma unroll
            for (int mt = 0; mt < 4; mt++)
#pragma unroll
                for (int nt = 0; nt < 4; nt++)
                    mma_f16(acc[mt][nt], af[mt][0], af[mt][1], af[mt][2], af[mt][3],
                            bf[nt][0], bf[nt][1]);
        }
        __syncthreads();
    }

    // Epilogue: c0,c1 at (row g, cols tig*2..); c2,c3 at row g+8.
#pragma unroll
    for (int mt = 0; mt < 4; mt++) {
        const int r_lo = row0 + wm * 64 + mt * 16 + g;
        const int r_hi = r_lo + 8;
#pragma unroll
        for (int nt = 0; nt < 4; nt++) {
            const int col = col0 + wn * 32 + nt * 8 + tig * 2;
            const float b0 = bias[col], b1 = bias[col + 1];
            if (CH) {
                __half* C = (__half*)Cp;
                *(uint32_t*)(C + (size_t)r_lo * N + col) =
                    pack2(acc[mt][nt][0] + b0, acc[mt][nt][1] + b1);
                *(uint32_t*)(C + (size_t)r_hi * N + col) =
                    pack2(acc[mt][nt][2] + b0, acc[mt][nt][3] + b1);
            } else {
                float* C = (float*)Cp;
                *(float2*)(C + (size_t)r_lo * N + col) =
                    make_float2(acc[mt][nt][0] + b0, acc[mt][nt][1] + b1);
                *(float2*)(C + (size_t)r_hi * N + col) =
                    make_float2(acc[mt][nt][2] + b0, acc[mt][nt][3] + b1);
            }
        }
    }
}

// ---------------- fp16 flash attention ----------------
// Grid (SEQ/128, BATCH*NUM_HEADS), 256 threads = 8 warps; warp owns 16 q-rows.
// Ks/Vs [64][72] halves (144B pitch). Qs aliases the pool during prologue.
__global__ __launch_bounds__(256) void attn_h()
{
    __shared__ __half pool[2 * 64 * 72];
    __half* Ks = pool;                 // [64][72]
    __half* Vs = pool + 64 * 72;       // [64][72]
    __half* Qs = pool;                 // [128][72] prologue alias (exact fit)

    const int tid = threadIdx.x, warp = tid >> 5, lane = tid & 31;
    const int g = lane >> 2, tig = lane & 3;
    const int bh = blockIdx.y, b = bh >> 4, h = bh & 15;
    const int q0 = blockIdx.x * 128;

    const __half* base = g_qkv + (size_t)b * SEQ * QKV_N;
    const __half2 sc = __half2half2(__float2half(0.125f));   // 2^-3, exact

    // ---- Prologue: Q tile (scaled) into Qs ----
    {
        const int r = tid >> 4, c4 = (tid & 15) * 4;
#pragma unroll
        for (int p = 0; p < 8; p++) {
            const int row = p * 16 + r;
            uint2 v = *(const uint2*)(base + (size_t)(q0 + row) * QKV_N + h * HEAD_SZ + c4);
            __half2 h0 = __hmul2(*(__half2*)&v.x, sc);
            __half2 h1 = __hmul2(*(__half2*)&v.y, sc);
            *(uint2*)&Qs[row * 72 + c4] = make_uint2(*(uint32_t*)&h0, *(uint32_t*)&h1);
        }
    }
    __syncthreads();

    // ---- Q fragments: 4 k16-steps ----
    uint32_t qf[4][4];
    {
        const uint32_t qBase = smem_u32(Qs) +
            (uint32_t)((warp * 16 + (lane & 7) + ((lane >> 3) & 1) * 8) * 144 + (lane >> 4) * 16);
#pragma unroll
        for (int kk = 0; kk < 4; kk++)
            LDSM4(qf[kk][0], qf[kk][1], qf[kk][2], qf[kk][3], qBase + kk * 32);
    }
    __syncthreads();   // pool reused for K/V

    float o[8][4];
#pragma unroll
    for (int nd = 0; nd < 8; nd++)
#pragma unroll
        for (int i = 0; i < 4; i++) o[nd][i] = 0.0f;
    float m_lo = -1e30f, m_hi = -1e30f, l_lo = 0.0f, l_hi = 0.0f;

    const int lr = tid >> 4, lc4 = (tid & 15) * 4;
    const uint32_t kBase = smem_u32(Ks) + (uint32_t)((lane & 7) * 144 + (lane >> 3) * 16);
    const uint32_t vBase = smem_u32(Vs) +
        (uint32_t)(((lane & 7) + ((lane >> 3) & 1) * 8) * 144 + (lane >> 4) * 16);

    for (int kb = 0; kb < SEQ; kb += 64) {
        // ---- K/V tiles (64x64 halves each) ----
#pragma unroll
        for (int p = 0; p < 4; p++) {
            const int row = p * 16 + lr;
            *(uint2*)&Ks[row * 72 + lc4] =
                *(const uint2*)(base + (size_t)(kb + row) * QKV_N + HIDDEN + h * HEAD_SZ + lc4);
            *(uint2*)&Vs[row * 72 + lc4] =
                *(const uint2*)(base + (size_t)(kb + row) * QKV_N + 2 * HIDDEN + h * HEAD_SZ + lc4);
        }
        __syncthreads();

        // ---- S = Q @ K^T : 8 key-octets x 4 k16-steps ----
        float c[8][4];
#pragma unroll
        for (int nt = 0; nt < 8; nt++) {
            uint32_t bK[4][2];
#pragma unroll
            for (int j = 0; j < 2; j++)
                LDSM4(bK[2 * j][0], bK[2 * j][1], bK[2 * j + 1][0], bK[2 * j + 1][1],
                      kBase + nt * 1152 + j * 64);
            c[nt][0] = c[nt][1] = c[nt][2] = c[nt][3] = 0.0f;
#pragma unroll
            for (int kk = 0; kk < 4; kk++)
                mma_f16(c[nt], qf[kk][0], qf[kk][1], qf[kk][2], qf[kk][3],
                        bK[kk][0], bK[kk][1]);
        }

        // ---- online softmax (rows g / g+8 shared across 4-lane group) ----
        float tmx_lo = -1e30f, tmx_hi = -1e30f;
#pragma unroll
        for (int nt = 0; nt < 8; nt++) {
            tmx_lo = fmaxf(tmx_lo, fmaxf(c[nt][0], c[nt][1]));
            tmx_hi = fmaxf(tmx_hi, fmaxf(c[nt][2], c[nt][3]));
        }
        tmx_lo = fmaxf(tmx_lo, __shfl_xor_sync(0xffffffffu, tmx_lo, 1));
        tmx_lo = fmaxf(tmx_lo, __shfl_xor_sync(0xffffffffu, tmx_lo, 2));
        tmx_hi = fmaxf(tmx_hi, __shfl_xor_sync(0xffffffffu, tmx_hi, 1));
        tmx_hi = fmaxf(tmx_hi, __shfl_xor_sync(0xffffffffu, tmx_hi, 2));

        const float mn_lo = fmaxf(m_lo, tmx_lo), mn_hi = fmaxf(m_hi, tmx_hi);
        const float al_lo = __expf(m_lo - mn_lo), al_hi = __expf(m_hi - mn_hi);
        m_lo = mn_lo; m_hi = mn_hi;
        l_lo *= al_lo; l_hi *= al_hi;
#pragma unroll
        for (int nd = 0; nd < 8; nd++) {
            o[nd][0] *= al_lo; o[nd][1] *= al_lo;
            o[nd][2] *= al_hi; o[nd][3] *= al_hi;
        }

        // ---- P @ V : k16 per step; C-layout pairs ARE the A-layout pairs ----
#pragma unroll
        for (int kp = 0; kp < 4; kp++) {
            float p00 = __expf(c[2 * kp][0] - m_lo), p01 = __expf(c[2 * kp][1] - m_lo);
            float p02 = __expf(c[2 * kp][2] - m_hi), p03 = __expf(c[2 * kp][3] - m_hi);
            float p10 = __expf(c[2 * kp + 1][0] - m_lo), p11 = __expf(c[2 * kp + 1][1] - m_lo);
            float p12 = __expf(c[2 * kp + 1][2] - m_hi), p13 = __expf(c[2 * kp + 1][3] - m_hi);
            l_lo += p00 + p01 + p10 + p11;
            l_hi += p02 + p03 + p12 + p13;
            const uint32_t a0 = pack2(p00, p01), a1 = pack2(p02, p03);
            const uint32_t a2 = pack2(p10, p11), a3 = pack2(p12, p13);

            uint32_t vb[8][2];
#pragma unroll
            for (int ndp = 0; ndp < 4; ndp++)
                LDSM4T(vb[2 * ndp][0], vb[2 * ndp][1], vb[2 * ndp + 1][0], vb[2 * ndp + 1][1],
                       vBase + kp * 2304 + ndp * 32);
#pragma unroll
            for (int nd = 0; nd < 8; nd++)
                mma_f16(o[nd], a0, a1, a2, a3, vb[nd][0], vb[nd][1]);
        }
        __syncthreads();
    }

    // ---- normalize + store (fp16) ----
    l_lo += __shfl_xor_sync(0xffffffffu, l_lo, 1);
    l_lo += __shfl_xor_sync(0xffffffffu, l_lo, 2);
    l_hi += __shfl_xor_sync(0xffffffffu, l_hi, 1);
    l_hi += __shfl_xor_sync(0xffffffffu, l_hi, 2);
    const float inv_lo = 1.0f / l_lo, inv_hi = 1.0f / l_hi;

    const int r_lo = q0 + warp * 16 + g, r_hi = r_lo + 8;
    __half* avb = g_av + (size_t)b * SEQ * HIDDEN + h * HEAD_SZ;
#pragma unroll
    for (int nd = 0; nd < 8; nd++) {
        const int col = nd * 8 + tig * 2;
        *(uint32_t*)(avb + (size_t)r_lo * HIDDEN + col) =
            pack2(o[nd][0] * inv_lo, o[nd][1] * inv_lo);
        *(uint32_t*)(avb + (size_t)r_hi * HIDDEN + col) =
            pack2(o[nd][2] * inv_hi, o[nd][3] * inv_hi);
    }
}

// ---------------- launch ----------------
extern "C" void kernel_launch(void* const* d_in, const int* in_sizes, int n_in,
                              void* d_out, int out_size)
{
    const float* x     = (const float*)d_in[0];
    const float* W_qkv = (const float*)d_in[1];
    const float* b_qkv = (const float*)d_in[2];
    const float* W_o   = (const float*)d_in[3];
    const float* b_o   = (const float*)d_in[4];

    __half *qkv, *av, *wt;
    cudaGetSymbolAddress((void**)&qkv, g_qkv);
    cudaGetSymbolAddress((void**)&av, g_av);
    cudaGetSymbolAddress((void**)&wt, g_wt);
    __half* wqkvT = wt;                               // [3072][1024]
    __half* woT   = wt + (size_t)QKV_N * HIDDEN;      // [1024][1024]

    transpose_h<<<dim3(QKV_N / 32, HIDDEN / 32), 256>>>(W_qkv, wqkvT, HIDDEN, QKV_N);
    transpose_h<<<dim3(HIDDEN / 32, HIDDEN / 32), 256>>>(W_o, woT, HIDDEN, HIDDEN);

    // 1) qkv (fp16) = x @ W_qkv + b_qkv
    gemm_h<false, true><<<dim3(QKV_N / 128, MTOT / 128), 256>>>(
        x, wqkvT, b_qkv, qkv, MTOT, QKV_N, HIDDEN);

    // 2) attention -> av (fp16)
    attn_h<<<dim3(SEQ / 128, BATCH * NUM_HEADS), 256>>>();

    // 3) out (fp32) = av @ W_o + b_o
    gemm_h<true, false><<<dim3(HIDDEN / 128, MTOT / 128), 256>>>(
        av, woT, b_o, d_out, MTOT, HIDDEN, HIDDEN);
}

// round 6
// speedup vs baseline: 1.5300x; 1.0012x over previous
#include <cuda_runtime.h>
#include <cuda_fp16.h>
#include <cstdint>

#define HIDDEN   1024
#define NUM_HEADS 16
#define HEAD_SZ   64
#define BATCH      2
#define SEQ     2048
#define MTOT    (BATCH * SEQ)
#define QKV_N   (3 * HIDDEN)

// Scratch (allocation-free rule: __device__ globals), fp16
__device__ __half g_qkv[(size_t)MTOT * QKV_N];                                // 24 MB
__device__ __half g_av [(size_t)MTOT * HIDDEN];                               // 8 MB
__device__ __half g_wt [(size_t)QKV_N * HIDDEN + (size_t)HIDDEN * HIDDEN];    // 10 MB

// ---------------- helpers ----------------
__device__ __forceinline__ uint32_t smem_u32(const void* p) {
    uint32_t a;
    asm("{ .reg .u64 t; cvta.to.shared.u64 t, %1; cvt.u32.u64 %0, t; }" : "=r"(a) : "l"(p));
    return a;
}
__device__ __forceinline__ uint32_t pack2(float lo, float hi) {
    __half2 h = __floats2half2_rn(lo, hi);
    return *(uint32_t*)&h;
}
__device__ __forceinline__ void mma_f16(float c[4],
    uint32_t a0, uint32_t a1, uint32_t a2, uint32_t a3, uint32_t b0, uint32_t b1)
{
    asm volatile(
        "mma.sync.aligned.m16n8k16.row.col.f32.f16.f16.f32 "
        "{%0,%1,%2,%3}, {%4,%5,%6,%7}, {%8,%9}, {%0,%1,%2,%3};\n"
        : "+f"(c[0]), "+f"(c[1]), "+f"(c[2]), "+f"(c[3])
        : "r"(a0), "r"(a1), "r"(a2), "r"(a3), "r"(b0), "r"(b1));
}
#define LDSM4(r0, r1, r2, r3, addr) \
    asm volatile("ldmatrix.sync.aligned.m8n8.x4.shared.b16 {%0,%1,%2,%3}, [%4];" \
        : "=r"(r0), "=r"(r1), "=r"(r2), "=r"(r3) : "r"(addr))
#define LDSM4T(r0, r1, r2, r3, addr) \
    asm volatile("ldmatrix.sync.aligned.m8n8.x4.trans.shared.b16 {%0,%1,%2,%3}, [%4];" \
        : "=r"(r0), "=r"(r1), "=r"(r2), "=r"(r3) : "r"(addr))

// ---------------- transpose W[R][C] (fp32) -> T[C][R] (fp16) ----------------
__global__ __launch_bounds__(256) void transpose_h(
    const float* __restrict__ W, __half* __restrict__ T, int R, int C)
{
    __shared__ float t[32][33];
    const int tx = threadIdx.x & 31, ty = threadIdx.x >> 5;
    const int c0 = blockIdx.x * 32, r0 = blockIdx.y * 32;
#pragma unroll
    for (int j = 0; j < 4; j++)
        t[ty + 8 * j][tx] = W[(size_t)(r0 + ty + 8 * j) * C + c0 + tx];
    __syncthreads();
#pragma unroll
    for (int j = 0; j < 4; j++)
        T[(size_t)(c0 + ty + 8 * j) * R + r0 + tx] = __float2half(t[tx][ty + 8 * j]);
}

// ---------------- fp16 GEMM: C[M,N] = A[M,K] @ BT[N,K]^T + bias ----------------
// Block 128x128, BK=32, 8 warps (2x4), warp tile 64x32, ldmatrix fragments.
// Smem pitch 40 halves (80B): 16B-aligned rows, conflict-free ldmatrix.
template<bool AH, bool CH>
__global__ __launch_bounds__(256) void gemm_h(
    const void* __restrict__ Ap, const __half* __restrict__ BT,
    const float* __restrict__ bias, void* __restrict__ Cp,
    int M, int N, int K)
{
    __shared__ __half As[128][40];
    __shared__ __half Bs[128][40];

    const int tid = threadIdx.x, warp = tid >> 5, lane = tid & 31;
    const int wm = warp >> 2, wn = warp & 3;
    const int g = lane >> 2, tig = lane & 3;
    const int row0 = blockIdx.y * 128, col0 = blockIdx.x * 128;
    const int frow = tid >> 3, kq = (tid & 7) * 4;

    const __half* Ah = (const __half*)Ap + (size_t)(row0 + frow) * K + kq;
    const float*  Af = (const float*)Ap + (size_t)(row0 + frow) * K + kq;
    const __half* Bh = BT + (size_t)(col0 + frow) * K + kq;

    float acc[4][4][4];
#pragma unroll
    for (int mt = 0; mt < 4; mt++)
#pragma unroll
        for (int nt = 0; nt < 4; nt++)
#pragma unroll
            for (int i = 0; i < 4; i++) acc[mt][nt][i] = 0.0f;

    const uint32_t aBase = smem_u32(&As[0][0]) +
        (uint32_t)((wm * 64 + (lane & 7) + ((lane >> 3) & 1) * 8) * 80 + (lane >> 4) * 16);
    const uint32_t bBase = smem_u32(&Bs[0][0]) +
        (uint32_t)((wn * 32 + (lane & 7) + (lane >> 4) * 8) * 80 + ((lane >> 3) & 1) * 16);

    uint2 aS[4], bS[4];
#pragma unroll
    for (int it = 0; it < 4; it++) {
        if (AH) aS[it] = *(const uint2*)(Ah + (size_t)(it * 32) * K);
        else {
            float4 v = *(const float4*)(Af + (size_t)(it * 32) * K);
            aS[it] = make_uint2(pack2(v.x, v.y), pack2(v.z, v.w));
        }
        bS[it] = *(const uint2*)(Bh + (size_t)(it * 32) * K);
    }

    const int nk = K >> 5;
    for (int kc = 0; kc < nk; kc++) {
#pragma unroll
        for (int it = 0; it < 4; it++) {
            *(uint2*)&As[it * 32 + frow][kq] = aS[it];
            *(uint2*)&Bs[it * 32 + frow][kq] = bS[it];
        }
        __syncthreads();
        if (kc + 1 < nk) {
            const int ko = (kc + 1) * 32;
#pragma unroll
            for (int it = 0; it < 4; it++) {
                if (AH) aS[it] = *(const uint2*)(Ah + (size_t)(it * 32) * K + ko);
                else {
                    float4 v = *(const float4*)(Af + (size_t)(it * 32) * K + ko);
                    aS[it] = make_uint2(pack2(v.x, v.y), pack2(v.z, v.w));
                }
                bS[it] = *(const uint2*)(Bh + (size_t)(it * 32) * K + ko);
            }
        }
#pragma unroll
        for (int kk = 0; kk < 2; kk++) {
            uint32_t af[4][4], bf[4][2];
#pragma unroll
            for (int mt = 0; mt < 4; mt++)
                LDSM4(af[mt][0], af[mt][1], af[mt][2], af[mt][3],
                      aBase + mt * 1280 + kk * 32);
#pragma unroll
            for (int ntp = 0; ntp < 2; ntp++)
                LDSM4(bf[2 * ntp][0], bf[2 * ntp][1], bf[2 * ntp + 1][0], bf[2 * ntp + 1][1],
                      bBase + ntp * 1280 + kk * 32);
#pragma unroll
            for (int mt = 0; mt < 4; mt++)
#pragma unroll
                for (int nt = 0; nt < 4; nt++)
                    mma_f16(acc[mt][nt], af[mt][0], af[mt][1], af[mt][2], af[mt][3],
                            bf[nt][0], bf[nt][1]);
        }
        __syncthreads();
    }

    // Epilogue: c0,c1 at (row g, cols tig*2..); c2,c3 at row g+8.
#pragma unroll
    for (int mt = 0; mt < 4; mt++) {
        const int r_lo = row0 + wm * 64 + mt * 16 + g;
        const int r_hi = r_lo + 8;
#pragma unroll
        for (int nt = 0; nt < 4; nt++) {
            const int col = col0 + wn * 32 + nt * 8 + tig * 2;
            const float b0 = bias[col], b1 = bias[col + 1];
            if (CH) {
                __half* C = (__half*)Cp;
                *(uint32_t*)(C + (size_t)r_lo * N + col) =
                    pack2(acc[mt][nt][0] + b0, acc[mt][nt][1] + b1);
                *(uint32_t*)(C + (size_t)r_hi * N + col) =
                    pack2(acc[mt][nt][2] + b0, acc[mt][nt][3] + b1);
            } else {
                float* C = (float*)Cp;
                *(float2*)(C + (size_t)r_lo * N + col) =
                    make_float2(acc[mt][nt][0] + b0, acc[mt][nt][1] + b1);
                *(float2*)(C + (size_t)r_hi * N + col) =
                    make_float2(acc[mt][nt][2] + b0, acc[mt][nt][3] + b1);
            }
        }
    }
}

// ---------------- fp16 flash attention ----------------
// Grid (SEQ/128, BATCH*NUM_HEADS), 256 threads = 8 warps; warp owns 16 q-rows.
// Ks/Vs [64][72] halves (144B pitch). Qs aliases the pool during prologue.
__global__ __launch_bounds__(256) void attn_h()
{
    __shared__ __half pool[2 * 64 * 72];
    __half* Ks = pool;                 // [64][72]
    __half* Vs = pool + 64 * 72;       // [64][72]
    __half* Qs = pool;                 // [128][72] prologue alias (exact fit)

    const int tid = threadIdx.x, warp = tid >> 5, lane = tid & 31;
    const int g = lane >> 2, tig = lane & 3;
    const int bh = blockIdx.y, b = bh >> 4, h = bh & 15;
    const int q0 = blockIdx.x * 128;

    const __half* base = g_qkv + (size_t)b * SEQ * QKV_N;
    const __half2 sc = __half2half2(__float2half(0.125f));   // 2^-3, exact

    // ---- Prologue: Q tile (scaled) into Qs ----
    {
        const int r = tid >> 4, c4 = (tid & 15) * 4;
#pragma unroll
        for (int p = 0; p < 8; p++) {
            const int row = p * 16 + r;
            uint2 v = *(const uint2*)(base + (size_t)(q0 + row) * QKV_N + h * HEAD_SZ + c4);
            __half2 h0 = __hmul2(*(__half2*)&v.x, sc);
            __half2 h1 = __hmul2(*(__half2*)&v.y, sc);
            *(uint2*)&Qs[row * 72 + c4] = make_uint2(*(uint32_t*)&h0, *(uint32_t*)&h1);
        }
    }
    __syncthreads();

    // ---- Q fragments: 4 k16-steps ----
    uint32_t qf[4][4];
    {
        const uint32_t qBase = smem_u32(Qs) +
            (uint32_t)((warp * 16 + (lane & 7) + ((lane >> 3) & 1) * 8) * 144 + (lane >> 4) * 16);
#pragma unroll
        for (int kk = 0; kk < 4; kk++)
            LDSM4(qf[kk][0], qf[kk][1], qf[kk][2], qf[kk][3], qBase + kk * 32);
    }
    __syncthreads();   // pool reused for K/V

    float o[8][4];
#pragma unroll
    for (int nd = 0; nd < 8; nd++)
#pragma unroll
        for (int i = 0; i < 4; i++) o[nd][i] = 0.0f;
    float m_lo = -1e30f, m_hi = -1e30f, l_lo = 0.0f, l_hi = 0.0f;

    const int lr = tid >> 4, lc4 = (tid & 15) * 4;
    const uint32_t kBase = smem_u32(Ks) + (uint32_t)((lane & 7) * 144 + (lane >> 3) * 16);
    const uint32_t vBase = smem_u32(Vs) +
        (uint32_t)(((lane & 7) + ((lane >> 3) & 1) * 8) * 144 + (lane >> 4) * 16);

    for (int kb = 0; kb < SEQ; kb += 64) {
        // ---- K/V tiles (64x64 halves each) ----
#pragma unroll
        for (int p = 0; p < 4; p++) {
            const int row = p * 16 + lr;
            *(uint2*)&Ks[row * 72 + lc4] =
                *(const uint2*)(base + (size_t)(kb + row) * QKV_N + HIDDEN + h * HEAD_SZ + lc4);
            *(uint2*)&Vs[row * 72 + lc4] =
                *(const uint2*)(base + (size_t)(kb + row) * QKV_N + 2 * HIDDEN + h * HEAD_SZ + lc4);
        }
        __syncthreads();

        // ---- S = Q @ K^T : 8 key-octets x 4 k16-steps ----
        float c[8][4];
#pragma unroll
        for (int nt = 0; nt < 8; nt++) {
            uint32_t bK[4][2];
#pragma unroll
            for (int j = 0; j < 2; j++)
                LDSM4(bK[2 * j][0], bK[2 * j][1], bK[2 * j + 1][0], bK[2 * j + 1][1],
                      kBase + nt * 1152 + j * 64);
            c[nt][0] = c[nt][1] = c[nt][2] = c[nt][3] = 0.0f;
#pragma unroll
            for (int kk = 0; kk < 4; kk++)
                mma_f16(c[nt], qf[kk][0], qf[kk][1], qf[kk][2], qf[kk][3],
                        bK[kk][0], bK[kk][1]);
        }

        // ---- online softmax (rows g / g+8 shared across 4-lane group) ----
        float tmx_lo = -1e30f, tmx_hi = -1e30f;
#pragma unroll
        for (int nt = 0; nt < 8; nt++) {
            tmx_lo = fmaxf(tmx_lo, fmaxf(c[nt][0], c[nt][1]));
            tmx_hi = fmaxf(tmx_hi, fmaxf(c[nt][2], c[nt][3]));
        }
        tmx_lo = fmaxf(tmx_lo, __shfl_xor_sync(0xffffffffu, tmx_lo, 1));
        tmx_lo = fmaxf(tmx_lo, __shfl_xor_sync(0xffffffffu, tmx_lo, 2));
        tmx_hi = fmaxf(tmx_hi, __shfl_xor_sync(0xffffffffu, tmx_hi, 1));
        tmx_hi = fmaxf(tmx_hi, __shfl_xor_sync(0xffffffffu, tmx_hi, 2));

        const float mn_lo = fmaxf(m_lo, tmx_lo), mn_hi = fmaxf(m_hi, tmx_hi);
        const float al_lo = __expf(m_lo - mn_lo), al_hi = __expf(m_hi - mn_hi);
        m_lo = mn_lo; m_hi = mn_hi;
        l_lo *= al_lo; l_hi *= al_hi;
#pragma unroll
        for (int nd = 0; nd < 8; nd++) {
            o[nd][0] *= al_lo; o[nd][1] *= al_lo;
            o[nd][2] *= al_hi; o[nd][3] *= al_hi;
        }

        // ---- P @ V : k16 per step; C-layout pairs ARE the A-layout pairs ----
#pragma unroll
        for (int kp = 0; kp < 4; kp++) {
            float p00 = __expf(c[2 * kp][0] - m_lo), p01 = __expf(c[2 * kp][1] - m_lo);
            float p02 = __expf(c[2 * kp][2] - m_hi), p03 = __expf(c[2 * kp][3] - m_hi);
            float p10 = __expf(c[2 * kp + 1][0] - m_lo), p11 = __expf(c[2 * kp + 1][1] - m_lo);
            float p12 = __expf(c[2 * kp + 1][2] - m_hi), p13 = __expf(c[2 * kp + 1][3] - m_hi);
            l_lo += p00 + p01 + p10 + p11;
            l_hi += p02 + p03 + p12 + p13;
            const uint32_t a0 = pack2(p00, p01), a1 = pack2(p02, p03);
            const uint32_t a2 = pack2(p10, p11), a3 = pack2(p12, p13);

            uint32_t vb[8][2];
#pragma unroll
            for (int ndp = 0; ndp < 4; ndp++)
                LDSM4T(vb[2 * ndp][0], vb[2 * ndp][1], vb[2 * ndp + 1][0], vb[2 * ndp + 1][1],
                       vBase + kp * 2304 + ndp * 32);
#pragma unroll
            for (int nd = 0; nd < 8; nd++)
                mma_f16(o[nd], a0, a1, a2, a3, vb[nd][0], vb[nd][1]);
        }
        __syncthreads();
    }

    // ---- normalize + store (fp16) ----
    l_lo += __shfl_xor_sync(0xffffffffu, l_lo, 1);
    l_lo += __shfl_xor_sync(0xffffffffu, l_lo, 2);
    l_hi += __shfl_xor_sync(0xffffffffu, l_hi, 1);
    l_hi += __shfl_xor_sync(0xffffffffu, l_hi, 2);
    const float inv_lo = 1.0f / l_lo, inv_hi = 1.0f / l_hi;

    const int r_lo = q0 + warp * 16 + g, r_hi = r_lo + 8;
    __half* avb = g_av + (size_t)b * SEQ * HIDDEN + h * HEAD_SZ;
#pragma unroll
    for (int nd = 0; nd < 8; nd++) {
        const int col = nd * 8 + tig * 2;
        *(uint32_t*)(avb + (size_t)r_lo * HIDDEN + col) =
            pack2(o[nd][0] * inv_lo, o[nd][1] * inv_lo);
        *(uint32_t*)(avb + (size_t)r_hi * HIDDEN + col) =
            pack2(o[nd][2] * inv_hi, o[nd][3] * inv_hi);
    }
}

// ---------------- launch ----------------
extern "C" void kernel_launch(void* const* d_in, const int* in_sizes, int n_in,
                              void* d_out, int out_size)
{
    const float* x     = (const float*)d_in[0];
    const float* W_qkv = (const float*)d_in[1];
    const float* b_qkv = (const float*)d_in[2];
    const float* W_o   = (const float*)d_in[3];
    const float* b_o   = (const float*)d_in[4];

    __half *qkv, *av, *wt;
    cudaGetSymbolAddress((void**)&qkv, g_qkv);
    cudaGetSymbolAddress((void**)&av, g_av);
    cudaGetSymbolAddress((void**)&wt, g_wt);
    __half* wqkvT = wt;                               // [3072][1024]
    __half* woT   = wt + (size_t)QKV_N * HIDDEN;      // [1024][1024]

    transpose_h<<<dim3(QKV_N / 32, HIDDEN / 32), 256>>>(W_qkv, wqkvT, HIDDEN, QKV_N);
    transpose_h<<<dim3(HIDDEN / 32, HIDDEN / 32), 256>>>(W_o, woT, HIDDEN, HIDDEN);

    // 1) qkv (fp16) = x @ W_qkv + b_qkv
    gemm_h<false, true><<<dim3(QKV_N / 128, MTOT / 128), 256>>>(
        x, wqkvT, b_qkv, qkv, MTOT, QKV_N, HIDDEN);

    // 2) attention -> av (fp16)
    attn_h<<<dim3(SEQ / 128, BATCH * NUM_HEADS), 256>>>();

    // 3) out (fp32) = av @ W_o + b_o
    gemm_h<true, false><<<dim3(HIDDEN / 128, MTOT / 128), 256>>>(
        av, woT, b_o, d_out, MTOT, HIDDEN, HIDDEN);
}